// round 17
// baseline (speedup 1.0000x reference)
#include <cuda_runtime.h>
#include <cuda_bf16.h>
#include <cstdint>

#define TT  12
#define NN  50000
#define EE  800000
#define TN  (TT*NN)          /* 600000 */
#define FIN 128
#define HH  64

// ------------------------- static device scratch -------------------------
__device__ float d_xw[(size_t)TN*64];          // xs @ W_gcn
__device__ float d_cur[(size_t)TN*64];         // GCN output
__device__ float d_gicur[(size_t)TN*192];      // cur @ W_ih[:, :64]^T
__device__ float d_yring[(size_t)3*NN*192];    // y = h @ Ws ring
__device__ float d_gring[3*NN];                // attention scalar ring
__device__ float d_dinv[TN];
__device__ int   d_cnt[TN];
__device__ int   d_fill[TN];
__device__ int   d_rowptr[TN];
__device__ int   d_ebuf[(size_t)TT*EE];
__device__ float d_WsQ[64*256];                // [k][0..191]=W_ih[j][64+k]; [k][192+c]=Q[c][k]
__device__ int   d_bsum[1024];
// bf16 hi/lo split weights for MMA GEMMs (B operand layout: [out][k] = col-major)
__device__ unsigned short d_Wg_h[64*128], d_Wg_l[64*128];   // W_gcn^T
__device__ unsigned short d_Wc_h[192*64], d_Wc_l[192*64];   // W_ih[:, :64]

// ------------------------- helpers -------------------------
__device__ __forceinline__ void ffma2(unsigned long long& d,
                                      unsigned long long a,
                                      unsigned long long b)
{
    asm("fma.rn.f32x2 %0, %1, %2, %0;" : "+l"(d) : "l"(a), "l"(b));
}

__device__ __forceinline__ float2 u2f2(unsigned long long u)
{
    float2 f;
    asm("mov.b64 {%0,%1}, %2;" : "=f"(f.x), "=f"(f.y) : "l"(u));
    return f;
}

__device__ __forceinline__ float sigf(float x)
{
    return 1.0f / (1.0f + __expf(-x));
}

__device__ __forceinline__ uint32_t smem_u32(const void* p)
{
    uint32_t a;
    asm("{ .reg .u64 t; cvta.to.shared.u64 t, %1; cvt.u32.u64 %0, t; }" : "=r"(a) : "l"(p));
    return a;
}

__device__ __forceinline__ void bsplit(float x, unsigned short& h, unsigned short& l)
{
    __nv_bfloat16 hb = __float2bfloat16(x);
    float hf = __bfloat162float(hb);
    __nv_bfloat16 lb = __float2bfloat16(x - hf);
    h = *(unsigned short*)&hb;
    l = *(unsigned short*)&lb;
}

#define SWZ(b) ((b) ^ (((b) >> 3) & 0x70))

__device__ __forceinline__ void ldm_x4(uint32_t* r, uint32_t addr)
{
    asm volatile("ldmatrix.sync.aligned.m8n8.x4.shared.b16 {%0,%1,%2,%3}, [%4];"
                 : "=r"(r[0]), "=r"(r[1]), "=r"(r[2]), "=r"(r[3]) : "r"(addr));
}

__device__ __forceinline__ void ldm_x2(uint32_t* r, uint32_t addr)
{
    asm volatile("ldmatrix.sync.aligned.m8n8.x2.shared.b16 {%0,%1}, [%2];"
                 : "=r"(r[0]), "=r"(r[1]) : "r"(addr));
}

__device__ __forceinline__ void mma16816(float* d, const uint32_t* a, const uint32_t* b)
{
    asm volatile(
        "mma.sync.aligned.m16n8k16.row.col.f32.bf16.bf16.f32 "
        "{%0,%1,%2,%3}, {%4,%5,%6,%7}, {%8,%9}, {%0,%1,%2,%3};"
        : "+f"(d[0]), "+f"(d[1]), "+f"(d[2]), "+f"(d[3])
        : "r"(a[0]), "r"(a[1]), "r"(a[2]), "r"(a[3]), "r"(b[0]), "r"(b[1]));
}

// ------------------------- weight prep (fp32 + bf16 splits) -------------------------
__global__ void k_prep(const float* __restrict__ W_ih, const float* __restrict__ Q,
                       const float* __restrict__ W_gcn,
                       float* __restrict__ WsQ,
                       unsigned short* __restrict__ Wg_h, unsigned short* __restrict__ Wg_l,
                       unsigned short* __restrict__ Wc_h, unsigned short* __restrict__ Wc_l)
{
    int tid = threadIdx.x;
    for (int i = tid; i < 64*192; i += 256) {
        int k = i / 192, j = i % 192;
        WsQ[(size_t)k*256 + j] = W_ih[(size_t)j*128 + 64 + k];
    }
    for (int i = tid; i < 64*64; i += 256) {
        int k = i / 64, c = i % 64;
        WsQ[(size_t)k*256 + 192 + c] = Q[(size_t)c*64 + k];
    }
    for (int i = tid; i < 64*128; i += 256) {
        int o = i / 128, k = i % 128;
        bsplit(W_gcn[(size_t)k*64 + o], Wg_h[i], Wg_l[i]);
    }
    for (int i = tid; i < 192*64; i += 256) {
        int j = i / 64, k = i % 64;
        bsplit(W_ih[(size_t)j*128 + k], Wc_h[i], Wc_l[i]);
    }
}

// ------------------------- CSR build -------------------------
__global__ void k_count(const int* __restrict__ ei, int* __restrict__ cnt)
{
    int e = blockIdx.x*256 + threadIdx.x;
    int t = blockIdx.y;
    if (e < EE) {
        int dst = ei[(size_t)t*2*EE + EE + e];
        atomicAdd(&cnt[t*NN + dst], 1);
    }
}

__global__ void k_scan1(const int* __restrict__ cnt, int* __restrict__ incl,
                        int* __restrict__ bsum, int n)
{
    __shared__ int ws[32];
    int tid  = threadIdx.x;
    int i    = blockIdx.x*1024 + tid;
    int lane = tid & 31, wid = tid >> 5;
    int v = (i < n) ? cnt[i] : 0;
    int x = v;
#pragma unroll
    for (int o = 1; o < 32; o <<= 1) {
        int y = __shfl_up_sync(0xffffffffu, x, o);
        if (lane >= o) x += y;
    }
    if (lane == 31) ws[wid] = x;
    __syncthreads();
    if (wid == 0) {
        int s = ws[lane];
#pragma unroll
        for (int o = 1; o < 32; o <<= 1) {
            int y = __shfl_up_sync(0xffffffffu, s, o);
            if (lane >= o) s += y;
        }
        ws[lane] = s;
    }
    __syncthreads();
    if (wid > 0) x += ws[wid-1];
    if (i < n) incl[i] = x;
    if (tid == 1023) bsum[blockIdx.x] = x;
}

__global__ void k_scan2(int* __restrict__ bsum, int nb)
{
    __shared__ int ws[32];
    int tid  = threadIdx.x;
    int lane = tid & 31, wid = tid >> 5;
    int v = (tid < nb) ? bsum[tid] : 0;
    int x = v;
#pragma unroll
    for (int o = 1; o < 32; o <<= 1) {
        int y = __shfl_up_sync(0xffffffffu, x, o);
        if (lane >= o) x += y;
    }
    if (lane == 31) ws[wid] = x;
    __syncthreads();
    if (wid == 0) {
        int s = ws[lane];
#pragma unroll
        for (int o = 1; o < 32; o <<= 1) {
            int y = __shfl_up_sync(0xffffffffu, s, o);
            if (lane >= o) s += y;
        }
        ws[lane] = s;
    }
    __syncthreads();
    if (wid > 0) x += ws[wid-1];
    if (tid < nb) bsum[tid] = x - v;   // exclusive
}

__global__ void k_scan3(const int* __restrict__ cnt, int* __restrict__ incl_then_rowptr,
                        const int* __restrict__ bsum, int* __restrict__ fill,
                        float* __restrict__ dinv, int n)
{
    int i = blockIdx.x*1024 + threadIdx.x;
    if (i < n) {
        int c  = cnt[i];
        int ex = incl_then_rowptr[i] - c + bsum[blockIdx.x];
        incl_then_rowptr[i] = ex;
        fill[i] = ex;
        dinv[i] = rsqrtf(1.0f + (float)c);
    }
}

__global__ void k_fill(const int* __restrict__ ei, int* __restrict__ fill,
                       int* __restrict__ ebuf)
{
    int e = blockIdx.x*256 + threadIdx.x;
    int t = blockIdx.y;
    if (e < EE) {
        int src = ei[(size_t)t*2*EE + e];
        int dst = ei[(size_t)t*2*EE + EE + e];
        int pos = atomicAdd(&fill[t*NN + dst], 1);
        ebuf[pos] = t*NN + src;
    }
}

// ------------------------- gather (GCN aggregation), row range [0, M) -------------------------
__global__ void k_gather(const float* __restrict__ xw, const float* __restrict__ bg,
                         float* __restrict__ cur,
                         const int* __restrict__ rowptr, const int* __restrict__ cnt,
                         const float* __restrict__ dinv, const int* __restrict__ ebuf,
                         int M)
{
    int w    = blockIdx.x*8 + (threadIdx.x >> 5);
    int lane = threadIdx.x & 31;
    if (w >= M) return;
    int start = rowptr[w];
    int c     = cnt[w];
    int col   = 2*lane;
    float2 a0 = make_float2(0.f, 0.f), a1 = a0, a2 = a0, a3 = a0;
    for (int b0 = 0; b0 < c; b0 += 32) {
        int rem  = c - b0;
        int mcnt = rem < 32 ? rem : 32;
        int   idx = (lane < mcnt) ? ebuf[start + b0 + lane] : 0;
        float dv  = (lane < mcnt) ? dinv[idx] : 0.f;
        int e = 0;
        for (; e + 4 <= mcnt; e += 4) {
            int g0 = __shfl_sync(0xffffffffu, idx, e);
            int g1 = __shfl_sync(0xffffffffu, idx, e+1);
            int g2 = __shfl_sync(0xffffffffu, idx, e+2);
            int g3 = __shfl_sync(0xffffffffu, idx, e+3);
            float w0 = __shfl_sync(0xffffffffu, dv, e);
            float w1 = __shfl_sync(0xffffffffu, dv, e+1);
            float w2 = __shfl_sync(0xffffffffu, dv, e+2);
            float w3 = __shfl_sync(0xffffffffu, dv, e+3);
            float2 x0 = *(const float2*)&xw[(size_t)g0*64 + col];
            float2 x1 = *(const float2*)&xw[(size_t)g1*64 + col];
            float2 x2 = *(const float2*)&xw[(size_t)g2*64 + col];
            float2 x3 = *(const float2*)&xw[(size_t)g3*64 + col];
            a0.x += w0*x0.x; a0.y += w0*x0.y;
            a1.x += w1*x1.x; a1.y += w1*x1.y;
            a2.x += w2*x2.x; a2.y += w2*x2.y;
            a3.x += w3*x3.x; a3.y += w3*x3.y;
        }
        for (; e < mcnt; e++) {
            int   g  = __shfl_sync(0xffffffffu, idx, e);
            float wv = __shfl_sync(0xffffffffu, dv,  e);
            float2 x = *(const float2*)&xw[(size_t)g*64 + col];
            a0.x += wv*x.x; a0.y += wv*x.y;
        }
    }
    float ax = a0.x + a1.x + a2.x + a3.x;
    float ay = a0.y + a1.y + a2.y + a3.y;
    float ds = dinv[w];
    float2 s = *(const float2*)&xw[(size_t)w*64 + col];
    float2 o;
    o.x = ds*(ax + ds*s.x) + bg[col];
    o.y = ds*(ay + ds*s.y) + bg[col+1];
    *(float2*)&cur[(size_t)w*64 + col] = o;
}

// ------------------------- HMMA bf16-split GEMM: C[M, nbt*64] = A[M,K] @ B^T -------------------------
// mma.sync m16n8k16 row.col, A fp32 -> bf16 hi/lo in smem (SW128 128B rows),
// B pre-split bf16 global [n][k] (= col-major, trans-free ldmatrix).
// 8 warps in 4x2 grid, 32x32 per warp; 3 passes AhBh + AhBl + AlBh.
#define MM_A_HI 0
#define MM_A_LO 16384
#define MM_B_HI 32768
#define MM_B_LO 40960
#define MM_SMEM 49152

__global__ __launch_bounds__(256)
void k_mma(const float* __restrict__ A,
           const unsigned short* __restrict__ Bh, const unsigned short* __restrict__ Bl,
           float* __restrict__ C, int M, int K, int nbt)
{
    extern __shared__ __align__(1024) char sm[];
    uint32_t sb = smem_u32(sm);
    int tid  = threadIdx.x;
    int wid  = tid >> 5;
    int lane = tid & 31;
    int row0 = blockIdx.x * 128;
    int wr   = wid >> 1;          // warp row 0..3 (32 rows each)
    int wc   = wid & 1;           // warp col 0..1 (32 cols each)
    int ldc  = nbt * 64;

    // ldmatrix source offsets (within current 64-k chunk)
    int a_row = wr*32 + (lane & 15);          // + mt*16
    int a_col = (lane >> 4) * 8;              // + ks*16
    int b_row = wc*32 + (lane & 7);           // + nt*8
    int b_col = ((lane >> 3) & 1) * 8;        // + ks*16

    for (int cb = 0; cb < nbt; cb++) {
        float acc[2][4][4];
#pragma unroll
        for (int mt = 0; mt < 2; mt++)
#pragma unroll
            for (int nt = 0; nt < 4; nt++)
#pragma unroll
                for (int q = 0; q < 4; q++) acc[mt][nt][q] = 0.f;

        for (int kk = 0; kk < K; kk += 64) {
            if (kk | cb) __syncthreads();
            // ---- A fill: fp32 -> bf16 hi/lo (skip when panel reused) ----
            if (cb == 0 || K > 64) {
                int r  = tid >> 1;
                int kh = (tid & 1) * 32;
                bool ok = (row0 + r) < M;
                const float* arow = A + (size_t)(row0 + r)*K + kk + kh;
#pragma unroll
                for (int j = 0; j < 8; j++) {
                    float4 v = ok ? *(const float4*)(arow + j*4)
                                  : make_float4(0.f, 0.f, 0.f, 0.f);
                    unsigned short h0, l0, h1, l1, h2, l2, h3, l3;
                    bsplit(v.x, h0, l0); bsplit(v.y, h1, l1);
                    bsplit(v.z, h2, l2); bsplit(v.w, h3, l3);
                    uint32_t b0 = r*128 + (kh + j*4)*2;
                    uint32_t b1 = b0 + 4;
                    *(uint32_t*)(sm + MM_A_HI + SWZ(b0)) = (uint32_t)h0 | ((uint32_t)h1 << 16);
                    *(uint32_t*)(sm + MM_A_HI + SWZ(b1)) = (uint32_t)h2 | ((uint32_t)h3 << 16);
                    *(uint32_t*)(sm + MM_A_LO + SWZ(b0)) = (uint32_t)l0 | ((uint32_t)l1 << 16);
                    *(uint32_t*)(sm + MM_A_LO + SWZ(b1)) = (uint32_t)l2 | ((uint32_t)l3 << 16);
                }
            }
            // ---- B fill: 64 n-rows x 64 k, hi/lo ----
            for (int idx = tid; idx < 2048; idx += 256) {
                int r  = idx >> 5;
                int ku = idx & 31;
                size_t g = (size_t)(cb*64 + r)*K + kk + 2*ku;
                uint32_t b = r*128 + ku*4;
                *(uint32_t*)(sm + MM_B_HI + SWZ(b)) = *(const uint32_t*)(Bh + g);
                *(uint32_t*)(sm + MM_B_LO + SWZ(b)) = *(const uint32_t*)(Bl + g);
            }
            __syncthreads();

#pragma unroll
            for (int ks = 0; ks < 4; ks++) {
                uint32_t Ah[2][4], Al[2][4], Bfh[4][2], Bfl[4][2];
#pragma unroll
                for (int mt = 0; mt < 2; mt++) {
                    uint32_t byt = (uint32_t)(a_row + mt*16)*128 + (uint32_t)(a_col + ks*16)*2;
                    ldm_x4(Ah[mt], sb + MM_A_HI + SWZ(byt));
                    ldm_x4(Al[mt], sb + MM_A_LO + SWZ(byt));
                }
#pragma unroll
                for (int nt = 0; nt < 4; nt++) {
                    uint32_t byt = (uint32_t)(b_row + nt*8)*128 + (uint32_t)(b_col + ks*16)*2;
                    ldm_x2(Bfh[nt], sb + MM_B_HI + SWZ(byt));
                    ldm_x2(Bfl[nt], sb + MM_B_LO + SWZ(byt));
                }
#pragma unroll
                for (int mt = 0; mt < 2; mt++)
#pragma unroll
                    for (int nt = 0; nt < 4; nt++) {
                        mma16816(acc[mt][nt], Ah[mt], Bfh[nt]);
                        mma16816(acc[mt][nt], Ah[mt], Bfl[nt]);
                        mma16816(acc[mt][nt], Al[mt], Bfh[nt]);
                    }
            }
        }

        // ---- epilogue ----
#pragma unroll
        for (int mt = 0; mt < 2; mt++) {
            int r0 = row0 + wr*32 + mt*16 + (lane >> 2);
#pragma unroll
            for (int nt = 0; nt < 4; nt++) {
                int c = cb*64 + wc*32 + nt*8 + (lane & 3)*2;
                if (r0 < M)
                    *(float2*)&C[(size_t)r0*ldc + c] =
                        make_float2(acc[mt][nt][0], acc[mt][nt][1]);
                if (r0 + 8 < M)
                    *(float2*)&C[(size_t)(r0+8)*ldc + c] =
                        make_float2(acc[mt][nt][2], acc[mt][nt][3]);
            }
        }
    }
}

// ------------------------- FFMA2 GEMM v7 (round-14, per-step y-GEMM) -------------------------
#define BM 256
#define ASTRIDE 260
#define AOFF(k, r) ((k)*ASTRIDE + ((r) ^ ((((k) >> 2) & 7) << 2)))
#define BPOS(cp) (4*(cp) + ((((cp)) >> 2) << 2))
#define GSM_BYTES ((64*ASTRIDE + 64*160) * 4)      /* 107520 B */

__global__ __launch_bounds__(256, 2)
void k_gemm(const float* __restrict__ A, const float* __restrict__ B,
            float* __restrict__ C, int M, int K, int ldb, int ldc, int nblk,
            float* __restrict__ gbuf, const float* __restrict__ rv)
{
    extern __shared__ __align__(16) float smx[];
    float* As = smx;
    float* Bs = smx + 64*ASTRIDE;
    int tid   = threadIdx.x;
    int row0  = blockIdx.x * BM;
    int rbase = (tid >> 3) * 8;
    int c0    = (tid & 7) * 8;
    int cp0   = 4 * (tid & 7);

    int wrp  = tid >> 5;
    int lane = tid & 31;
    int half = lane >> 4;
    int l4   = lane & 15;
    int sw   = (l4 & 7) << 2;

    for (int cb = 0; cb < nblk; cb++) {
        int nb = cb * 64;
        unsigned long long acc[4][8];
#pragma unroll
        for (int i = 0; i < 4; i++)
#pragma unroll
            for (int j = 0; j < 8; j++) acc[i][j] = 0ull;

        for (int kk = 0; kk < K; kk += 64) {
            if (kk | cb) __syncthreads();
            if (cb == 0 || K > 64) {
#pragma unroll
                for (int rr = 0; rr < 16; rr += 4) {
                    float4 va[4];
#pragma unroll
                    for (int u = 0; u < 4; u++) {
                        int lr = wrp*32 + (rr + u)*2 + half;
                        int gr = row0 + lr;
                        va[u] = (gr < M) ? *(const float4*)&A[(size_t)gr*K + kk + 4*l4]
                                         : make_float4(0.f, 0.f, 0.f, 0.f);
                    }
#pragma unroll
                    for (int u = 0; u < 4; u++) {
                        int lr  = wrp*32 + (rr + u)*2 + half;
                        int rsw = lr ^ sw;
                        As[(4*l4 + 0)*ASTRIDE + rsw] = va[u].x;
                        As[(4*l4 + 1)*ASTRIDE + rsw] = va[u].y;
                        As[(4*l4 + 2)*ASTRIDE + rsw] = va[u].z;
                        As[(4*l4 + 3)*ASTRIDE + rsw] = va[u].w;
                    }
                }
            }
#pragma unroll
            for (int q = 0; q < 4; q++) {
                int idx = tid + q*256;
                int kb  = idx >> 4;
                int cq  = idx & 15;
                float4 w = *(const float4*)&B[(size_t)(kk + kb)*ldb + nb + cq*4];
                *(float4*)&Bs[kb*160 + BPOS(cq*2)]     = make_float4(w.x, w.x, w.y, w.y);
                *(float4*)&Bs[kb*160 + BPOS(cq*2 + 1)] = make_float4(w.z, w.z, w.w, w.w);
            }
            __syncthreads();
#pragma unroll
            for (int k = 0; k < 64; k++) {
                ulonglong2 a01 = *(const ulonglong2*)&As[AOFF(k, rbase)];
                ulonglong2 a23 = *(const ulonglong2*)&As[AOFF(k, rbase + 4)];
                ulonglong2 b0  = *(const ulonglong2*)&Bs[k*160 + BPOS(cp0)];
                ulonglong2 b1  = *(const ulonglong2*)&Bs[k*160 + BPOS(cp0) + 4];
                ulonglong2 b2  = *(const ulonglong2*)&Bs[k*160 + BPOS(cp0) + 8];
                ulonglong2 b3  = *(const ulonglong2*)&Bs[k*160 + BPOS(cp0) + 12];
                ffma2(acc[0][0], a01.x, b0.x); ffma2(acc[0][1], a01.x, b0.y);
                ffma2(acc[0][2], a01.x, b1.x); ffma2(acc[0][3], a01.x, b1.y);
                ffma2(acc[0][4], a01.x, b2.x); ffma2(acc[0][5], a01.x, b2.y);
                ffma2(acc[0][6], a01.x, b3.x); ffma2(acc[0][7], a01.x, b3.y);
                ffma2(acc[1][0], a01.y, b0.x); ffma2(acc[1][1], a01.y, b0.y);
                ffma2(acc[1][2], a01.y, b1.x); ffma2(acc[1][3], a01.y, b1.y);
                ffma2(acc[1][4], a01.y, b2.x); ffma2(acc[1][5], a01.y, b2.y);
                ffma2(acc[1][6], a01.y, b3.x); ffma2(acc[1][7], a01.y, b3.y);
                ffma2(acc[2][0], a23.x, b0.x); ffma2(acc[2][1], a23.x, b0.y);
                ffma2(acc[2][2], a23.x, b1.x); ffma2(acc[2][3], a23.x, b1.y);
                ffma2(acc[2][4], a23.x, b2.x); ffma2(acc[2][5], a23.x, b2.y);
                ffma2(acc[2][6], a23.x, b3.x); ffma2(acc[2][7], a23.x, b3.y);
                ffma2(acc[3][0], a23.y, b0.x); ffma2(acc[3][1], a23.y, b0.y);
                ffma2(acc[3][2], a23.y, b1.x); ffma2(acc[3][3], a23.y, b1.y);
                ffma2(acc[3][4], a23.y, b2.x); ffma2(acc[3][5], a23.y, b2.y);
                ffma2(acc[3][6], a23.y, b3.x); ffma2(acc[3][7], a23.y, b3.y);
            }
        }

        if (gbuf != nullptr && cb == 3) {
            float rr[8];
#pragma unroll
            for (int j = 0; j < 8; j++) rr[j] = rv[c0 + j];
#pragma unroll
            for (int i = 0; i < 4; i++) {
                float px = 0.f, py = 0.f;
#pragma unroll
                for (int j = 0; j < 8; j++) {
                    float2 v = u2f2(acc[i][j]);
                    px += rr[j] * tanhf(v.x);
                    py += rr[j] * tanhf(v.y);
                }
                px += __shfl_down_sync(0xffffffffu, px, 4);
                py += __shfl_down_sync(0xffffffffu, py, 4);
                px += __shfl_down_sync(0xffffffffu, px, 2);
                py += __shfl_down_sync(0xffffffffu, py, 2);
                px += __shfl_down_sync(0xffffffffu, px, 1);
                py += __shfl_down_sync(0xffffffffu, py, 1);
                if ((tid & 7) == 0) {
                    int n0 = row0 + rbase + 2*i;
                    if (n0 < M)     gbuf[n0]     = px;
                    if (n0 + 1 < M) gbuf[n0 + 1] = py;
                }
            }
        } else {
#pragma unroll
            for (int i = 0; i < 4; i++) {
                int n0 = row0 + rbase + 2*i;
                float2 v0 = u2f2(acc[i][0]), v1 = u2f2(acc[i][1]);
                float2 v2 = u2f2(acc[i][2]), v3 = u2f2(acc[i][3]);
                float2 v4 = u2f2(acc[i][4]), v5 = u2f2(acc[i][5]);
                float2 v6 = u2f2(acc[i][6]), v7 = u2f2(acc[i][7]);
                if (n0 < M) {
                    *(float4*)&C[(size_t)n0*ldc + nb + c0]     = make_float4(v0.x, v1.x, v2.x, v3.x);
                    *(float4*)&C[(size_t)n0*ldc + nb + c0 + 4] = make_float4(v4.x, v5.x, v6.x, v7.x);
                }
                if (n0 + 1 < M) {
                    *(float4*)&C[(size_t)(n0+1)*ldc + nb + c0]     = make_float4(v0.y, v1.y, v2.y, v3.y);
                    *(float4*)&C[(size_t)(n0+1)*ldc + nb + c0 + 4] = make_float4(v4.y, v5.y, v6.y, v7.y);
                }
            }
        }
    }
}

// ------------------------- per-step elementwise GRU v2 (float4, 16 lanes/node) -------------------------
__global__ __launch_bounds__(256)
void k_gru(int t,
           const float* __restrict__ gi_cur_t,
           const float* __restrict__ yring, const float* __restrict__ gring,
           const float* __restrict__ b_ih, const float* __restrict__ b_hh,
           float* __restrict__ out_t)
{
    int n  = blockIdx.x*16 + (threadIdx.x >> 4);
    int c0 = (threadIdx.x & 15) * 4;

    float e2 = (t >= 1) ? gring[((t-1)%3)*NN + n] : 0.0f;
    float e1 = (t >= 1) ? ((t >= 2) ? gring[((t-2)%3)*NN + n] : 0.0f) : -1e30f;
    float e0 = (t >= 2) ? ((t >= 3) ? gring[((t-3)%3)*NN + n] : 0.0f) : -1e30f;
    float mx = fmaxf(e2, fmaxf(e1, e0));
    float a0 = (t >= 2) ? __expf(e0 - mx) : 0.f;
    float a1 = (t >= 1) ? __expf(e1 - mx) : 0.f;
    float a2 = __expf(e2 - mx);
    float inv = 1.0f / (a0 + a1 + a2);
    a0 *= inv; a1 *= inv; a2 *= inv;

    const float* gc = &gi_cur_t[(size_t)n*192];
    float4 gr = *(const float4*)&gc[c0];
    float4 gz = *(const float4*)&gc[64 + c0];
    float4 gn = *(const float4*)&gc[128 + c0];

    if (t >= 1) {
        const float* y = &yring[(size_t)((t-1)%3)*NN*192 + (size_t)n*192];
        float4 yr = *(const float4*)&y[c0];
        float4 yz = *(const float4*)&y[64 + c0];
        float4 yn = *(const float4*)&y[128 + c0];
        gr.x += a2*yr.x; gr.y += a2*yr.y; gr.z += a2*yr.z; gr.w += a2*yr.w;
        gz.x += a2*yz.x; gz.y += a2*yz.y; gz.z += a2*yz.z; gz.w += a2*yz.w;
        gn.x += a2*yn.x; gn.y += a2*yn.y; gn.z += a2*yn.z; gn.w += a2*yn.w;
    }
    if (t >= 2) {
        const float* y = &yring[(size_t)((t-2)%3)*NN*192 + (size_t)n*192];
        float4 yr = *(const float4*)&y[c0];
        float4 yz = *(const float4*)&y[64 + c0];
        float4 yn = *(const float4*)&y[128 + c0];
        gr.x += a1*yr.x; gr.y += a1*yr.y; gr.z += a1*yr.z; gr.w += a1*yr.w;
        gz.x += a1*yz.x; gz.y += a1*yz.y; gz.z += a1*yz.z; gz.w += a1*yz.w;
        gn.x += a1*yn.x; gn.y += a1*yn.y; gn.z += a1*yn.z; gn.w += a1*yn.w;
    }
    if (t >= 3) {
        const float* y = &yring[(size_t)((t-3)%3)*NN*192 + (size_t)n*192];
        float4 yr = *(const float4*)&y[c0];
        float4 yz = *(const float4*)&y[64 + c0];
        float4 yn = *(const float4*)&y[128 + c0];
        gr.x += a0*yr.x; gr.y += a0*yr.y; gr.z += a0*yr.z; gr.w += a0*yr.w;
        gz.x += a0*yz.x; gz.y += a0*yz.y; gz.z += a0*yz.z; gz.w += a0*yz.w;
        gn.x += a0*yn.x; gn.y += a0*yn.y; gn.z += a0*yn.z; gn.w += a0*yn.w;
    }

    float4 bir = *(const float4*)&b_ih[c0];
    float4 biz = *(const float4*)&b_ih[64 + c0];
    float4 bin = *(const float4*)&b_ih[128 + c0];
    float4 bhr = *(const float4*)&b_hh[c0];
    float4 bhz = *(const float4*)&b_hh[64 + c0];
    float4 bhn = *(const float4*)&b_hh[128 + c0];

    float4 H;
    {
        float r0 = sigf(gr.x + bir.x + bhr.x);
        float z0 = sigf(gz.x + biz.x + bhz.x);
        float n0 = tanhf(gn.x + bin.x + r0*bhn.x);
        H.x = (1.0f - z0) * n0;
    }
    {
        float r0 = sigf(gr.y + bir.y + bhr.y);
        float z0 = sigf(gz.y + biz.y + bhz.y);
        float n0 = tanhf(gn.y + bin.y + r0*bhn.y);
        H.y = (1.0f - z0) * n0;
    }
    {
        float r0 = sigf(gr.z + bir.z + bhr.z);
        float z0 = sigf(gz.z + biz.z + bhz.z);
        float n0 = tanhf(gn.z + bin.z + r0*bhn.z);
        H.z = (1.0f - z0) * n0;
    }
    {
        float r0 = sigf(gr.w + bir.w + bhr.w);
        float z0 = sigf(gz.w + biz.w + bhz.w);
        float n0 = tanhf(gn.w + bin.w + r0*bhn.w);
        H.w = (1.0f - z0) * n0;
    }
    *(float4*)&out_t[(size_t)n*64 + c0] = H;
}

// ------------------------- launcher -------------------------
extern "C" void kernel_launch(void* const* d_in, const int* in_sizes, int n_in,
                              void* d_out, int out_size)
{
    const float* xs    = (const float*)d_in[0];
    const int*   ei    = (const int*)  d_in[1];
    const float* W_gcn = (const float*)d_in[2];
    const float* b_gcn = (const float*)d_in[3];
    const float* Q     = (const float*)d_in[4];
    const float* r_vec = (const float*)d_in[5];
    const float* W_ih  = (const float*)d_in[6];
    const float* b_ih  = (const float*)d_in[8];
    const float* b_hh  = (const float*)d_in[9];
    float* out = (float*)d_out;

    float *p_xw, *p_cur, *p_gic, *p_yr, *p_gr, *p_dinv, *p_WsQ;
    int   *p_cnt, *p_fill, *p_rp, *p_eb, *p_bs;
    unsigned short *p_Wgh, *p_Wgl, *p_Wch, *p_Wcl;
    cudaGetSymbolAddress((void**)&p_xw,   d_xw);
    cudaGetSymbolAddress((void**)&p_cur,  d_cur);
    cudaGetSymbolAddress((void**)&p_gic,  d_gicur);
    cudaGetSymbolAddress((void**)&p_yr,   d_yring);
    cudaGetSymbolAddress((void**)&p_gr,   d_gring);
    cudaGetSymbolAddress((void**)&p_dinv, d_dinv);
    cudaGetSymbolAddress((void**)&p_WsQ,  d_WsQ);
    cudaGetSymbolAddress((void**)&p_cnt,  d_cnt);
    cudaGetSymbolAddress((void**)&p_fill, d_fill);
    cudaGetSymbolAddress((void**)&p_rp,   d_rowptr);
    cudaGetSymbolAddress((void**)&p_eb,   d_ebuf);
    cudaGetSymbolAddress((void**)&p_bs,   d_bsum);
    cudaGetSymbolAddress((void**)&p_Wgh,  d_Wg_h);
    cudaGetSymbolAddress((void**)&p_Wgl,  d_Wg_l);
    cudaGetSymbolAddress((void**)&p_Wch,  d_Wc_h);
    cudaGetSymbolAddress((void**)&p_Wcl,  d_Wc_l);

    cudaFuncSetAttribute(k_gemm, cudaFuncAttributeMaxDynamicSharedMemorySize, GSM_BYTES);
    cudaFuncSetAttribute(k_mma,  cudaFuncAttributeMaxDynamicSharedMemorySize, MM_SMEM);

    const int nsb = (TN + 1023) / 1024;      // 586 scan blocks
    const int gx_mm = (TN + 127) / 128;      // 4688
    const int gx_y  = (NN + BM - 1) / BM;    // 196
    const int gx_gru = NN / 16;              // 3125

    cudaMemsetAsync(p_cnt, 0, (size_t)TN * sizeof(int));
    k_prep <<<1, 256>>>(W_ih, Q, W_gcn, p_WsQ, p_Wgh, p_Wgl, p_Wch, p_Wcl);  // launch 1
    k_count<<<dim3((EE + 255)/256, TT), 256>>>(ei, p_cnt);                   // launch 2

    // xw = xs @ W_gcn  via HMMA bf16-split (K=128, 1 col-tile)
    k_mma<<<gx_mm, 256, MM_SMEM>>>(xs, p_Wgh, p_Wgl, p_xw, TN, FIN, 1);      // launch 3

    // DIAGNOSTIC at profiled slot 4: dummy gicur-shaped k_mma. Reads d_cur
    // (zero-initialized on first run; previous replay's deterministic values
    // after). Writes only d_gicur, which the real k_mma below fully rewrites
    // before k_gru reads it. Output unaffected, deterministic.
    k_mma<<<gx_mm, 256, MM_SMEM>>>(p_cur, p_Wch, p_Wcl, p_gic, TN, HH, 3);   // launch 4

    k_scan1<<<nsb, 1024>>>(p_cnt, p_rp, p_bs, TN);                           // launch 5
    k_scan2<<<1, 1024>>>(p_bs, nsb);
    k_scan3<<<nsb, 1024>>>(p_cnt, p_rp, p_bs, p_fill, p_dinv, TN);
    k_fill <<<dim3((EE + 255)/256, TT), 256>>>(ei, p_fill, p_eb);

    k_gather<<<(TN + 7)/8, 256>>>(p_xw, b_gcn, p_cur, p_rp, p_cnt, p_dinv,
                                  p_eb, TN);

    // gi_cur = cur @ W_ih[:, :64]^T  via HMMA bf16-split (K=64, 3 col-tiles, A reused)
    k_mma<<<gx_mm, 256, MM_SMEM>>>(p_cur, p_Wch, p_Wcl, p_gic, TN, HH, 3);

    for (int t = 0; t < TT; t++) {
        int slot = t % 3;
        k_gru<<<gx_gru, 256>>>(t, p_gic + (size_t)t*NN*192, p_yr, p_gr,
                               b_ih, b_hh, out + (size_t)t*NN*64);
        k_gemm<<<gx_y, 256, GSM_BYTES>>>(out + (size_t)t*NN*64, p_WsQ,
                                         p_yr + (size_t)slot*NN*192, NN, HH, 256, 192, 4,
                                         p_gr + slot*NN, r_vec);
    }
}